// round 2
// baseline (speedup 1.0000x reference)
#include <cuda_runtime.h>
#include <cuda_bf16.h>
#include <math.h>

// Problem constants (fixed by setup_inputs)
#define BB   8
#define SS   4096
#define HH   1152
#define LEN  1024
#define KK   2          // pooling factor k = sqrt(S/LEN)
#define K2   4          // k*k
#define HV   (HH/4)     // float4 chunks per row = 288

// Scratch (allocation-free rule: __device__ globals)
__device__ int g_counts[BB * LEN];
__device__ int g_lists[BB * LEN * K2];
__device__ int g_maxx[BB];

// ---------------------------------------------------------------------------
// Kernel 0: zero segment counts (8192 ints)
__global__ void k_zero_counts() {
    int i = blockIdx.x * blockDim.x + threadIdx.x;
    if (i < BB * LEN) g_counts[i] = 0;
}

// ---------------------------------------------------------------------------
// Kernel 1: per-batch max_x over clamped x positions. One block per batch.
__global__ void k_maxx(const int* __restrict__ pos, int npos) {
    __shared__ int smax[8];
    int b = blockIdx.x;
    int m = 0;
    for (int s = threadIdx.x; s < SS; s += blockDim.x) {
        long long off = ((long long)b * SS + s) * 2;
        int x = (off < npos) ? pos[off] : 0;
        if (x < 0) x = 0;
        m = max(m, x);
    }
    for (int o = 16; o > 0; o >>= 1)
        m = max(m, __shfl_xor_sync(0xFFFFFFFFu, m, o));
    int wid = threadIdx.x >> 5;
    if ((threadIdx.x & 31) == 0) smax[wid] = m;
    __syncthreads();
    if (threadIdx.x == 0) {
        int r = smax[0];
        int nw = blockDim.x >> 5;
        for (int w = 1; w < nw; w++) r = max(r, smax[w]);
        g_maxx[b] = r + 1;
    }
}

// ---------------------------------------------------------------------------
// Kernel 2: build per-segment source lists from patch positions.
__global__ void k_build(const int* __restrict__ pos, int npos) {
    int i = blockIdx.x * blockDim.x + threadIdx.x;   // over B*S
    if (i >= BB * SS) return;
    int b = i / SS;
    int s = i - b * SS;
    long long off = (long long)i * 2;
    int x = (off + 1 < npos) ? pos[off]     : 0;
    int y = (off + 1 < npos) ? pos[off + 1] : 0;
    if (x < 0) x = 0;
    if (y < 0) y = 0;
    int mw = g_maxx[b] / KK;
    int seg = (x / KK) + mw * (y / KK);
    if (seg < 0) seg = 0;
    if (seg >= LEN) seg = LEN - 1;   // safety clamp
    int slot = atomicAdd(&g_counts[b * LEN + seg], 1);
    if (slot < K2) g_lists[(b * LEN + seg) * K2 + slot] = s;
}

// ---------------------------------------------------------------------------
// Kernel 3: gather-pool. One block per (b, seg); 288 threads, one float4 each.
// All writes bounds-checked against the harness-provided out_size.
__global__ __launch_bounds__(HV) void k_pool(const float* __restrict__ hs,
                                             float* __restrict__ out,
                                             long long out_elems) {
    int bs = blockIdx.x;                 // 0 .. B*LEN-1
    int b  = bs >> 10;                   // LEN = 1024
    int cnt = g_counts[bs];
    if (cnt > K2) cnt = K2;

    // Sort the 4-entry source list so fp32 summation order is deterministic
    // (atomicAdd slot order is not).
    int idxs[K2];
    #pragma unroll
    for (int j = 0; j < K2; j++)
        idxs[j] = (j < cnt) ? g_lists[bs * K2 + j] : 0x7FFFFFFF;
    #pragma unroll
    for (int a = 0; a < K2; a++)
        #pragma unroll
        for (int c = a + 1; c < K2; c++)
            if (idxs[c] < idxs[a]) { int t = idxs[a]; idxs[a] = idxs[c]; idxs[c] = t; }

    int t = threadIdx.x;
    float4 acc = make_float4(0.f, 0.f, 0.f, 0.f);
    const float4* base = (const float4*)(hs) + (size_t)b * SS * HV;
    #pragma unroll
    for (int j = 0; j < K2; j++) {
        if (j < cnt && idxs[j] < SS) {
            float4 v = base[(size_t)idxs[j] * HV + t];
            acc.x += v.x; acc.y += v.y; acc.z += v.z; acc.w += v.w;
        }
    }
    // scale = sqrt(1152) / k2
    const float scale = 8.485281374238571f;
    acc.x *= scale; acc.y *= scale; acc.z *= scale; acc.w *= scale;

    long long e = (long long)bs * HH + (long long)t * 4;  // scalar element index
    if (e + 3 < out_elems) {
        ((float4*)out)[(size_t)bs * HV + t] = acc;
    } else {
        // tail-safe scalar writes
        float v[4] = {acc.x, acc.y, acc.z, acc.w};
        #pragma unroll
        for (int q = 0; q < 4; q++)
            if (e + q < out_elems) out[e + q] = v[q];
    }
}

// ---------------------------------------------------------------------------
// Kernel 4: optional mask tail (counts > 0 as 1.0f) if out buffer extends
// beyond the pooled tensor. Fully bounds-checked.
__global__ void k_mask(float* __restrict__ out, long long start, long long out_elems) {
    long long i = (long long)blockIdx.x * blockDim.x + threadIdx.x;
    long long e = start + i;
    if (e >= out_elems) return;
    long long m = e - start;
    float v = 1.0f;
    if (m < BB * LEN) v = (g_counts[m] > 0) ? 1.0f : 0.0f;
    out[e] = v;
}

// ---------------------------------------------------------------------------
extern "C" void kernel_launch(void* const* d_in, const int* in_sizes, int n_in,
                              void* d_out, int out_size) {
    if (n_in < 2 || !d_in || !d_out) return;
    const float* hs  = (const float*)d_in[0];
    const int*   pos = (const int*)d_in[1];
    int npos = in_sizes[1];
    float* out = (float*)d_out;
    long long out_elems = (long long)out_size;

    k_zero_counts<<<(BB * LEN + 255) / 256, 256>>>();
    k_maxx<<<BB, 256>>>(pos, npos);
    k_build<<<(BB * SS + 255) / 256, 256>>>(pos, npos);
    k_pool<<<BB * LEN, HV>>>(hs, out, out_elems);

    long long nout = (long long)BB * LEN * HH;
    if (out_elems > nout) {
        long long extra = out_elems - nout;
        int blocks = (int)((extra + 255) / 256);
        k_mask<<<blocks, 256>>>(out, nout, out_elems);
    }
}

// round 5
// speedup vs baseline: 1.1360x; 1.1360x over previous
#include <cuda_runtime.h>
#include <cuda_bf16.h>
#include <math.h>

// Problem constants (fixed by setup_inputs)
#define BB   8
#define SS   4096
#define HH   1152
#define LEN  1024
#define KK   2          // pooling factor k = sqrt(S/LEN)
#define K2   4          // k*k
#define HV   (HH/4)     // float4 chunks per row = 288

// Scratch (allocation-free rule: __device__ globals)
__device__ int g_counts[BB * LEN];
__device__ int g_lists[BB * LEN * K2];

// ---------------------------------------------------------------------------
// Kernel 1: per-batch index build. One block per batch (8 blocks, 256 thr).
//  - reduce max_x over clamped positions
//  - build per-segment source lists with SMEM atomics
//  - dump counts + lists to global
//  - write the mask tail of the output directly (counts>0 as 1.0f)
__global__ __launch_bounds__(256) void k_index(const int* __restrict__ pos,
                                               int npos,
                                               float* __restrict__ out,
                                               long long out_elems) {
    __shared__ int s_counts[LEN];
    __shared__ int s_lists[LEN * K2];
    __shared__ int s_max[8];

    const int b   = blockIdx.x;
    const int tid = threadIdx.x;

    // zero counts
    for (int i = tid; i < LEN; i += 256) s_counts[i] = 0;

    // max_x reduction (clamped at 0)
    int m = 0;
    for (int s = tid; s < SS; s += 256) {
        long long off = ((long long)b * SS + s) * 2;
        int x = (off < npos) ? pos[off] : 0;
        if (x < 0) x = 0;
        m = max(m, x);
    }
    for (int o = 16; o > 0; o >>= 1)
        m = max(m, __shfl_xor_sync(0xFFFFFFFFu, m, o));
    if ((tid & 31) == 0) s_max[tid >> 5] = m;
    __syncthreads();
    if (tid == 0) {
        int r = s_max[0];
        for (int w = 1; w < 8; w++) r = max(r, s_max[w]);
        s_max[0] = (r + 1) / KK;   // max_x//k, the segment row width
    }
    __syncthreads();
    const int mw = s_max[0];

    // build lists (smem atomics); counts were zeroed before the barriers above
    for (int s = tid; s < SS; s += 256) {
        long long off = ((long long)b * SS + s) * 2;
        int x = (off + 1 < npos) ? pos[off]     : 0;
        int y = (off + 1 < npos) ? pos[off + 1] : 0;
        if (x < 0) x = 0;
        if (y < 0) y = 0;
        int seg = (x / KK) + mw * (y / KK);
        if (seg < 0) seg = 0;
        if (seg >= LEN) seg = LEN - 1;
        int slot = atomicAdd(&s_counts[seg], 1);
        if (slot < K2) s_lists[seg * K2 + slot] = s;
    }
    __syncthreads();

    // dump to global for k_pool
    for (int i = tid; i < LEN; i += 256)
        g_counts[b * LEN + i] = s_counts[i];
    for (int i = tid; i < LEN * K2; i += 256)
        g_lists[b * LEN * K2 + i] = s_lists[i];

    // mask tail: out[nout + b*LEN + seg] = counts>0 ? 1 : 0
    const long long nout = (long long)BB * LEN * HH;
    for (int i = tid; i < LEN; i += 256) {
        long long e = nout + (long long)b * LEN + i;
        if (e < out_elems)
            out[e] = (s_counts[i] > 0) ? 1.0f : 0.0f;
    }
    // any tail beyond BB*LEN (defensive): block 0 fills with 1.0
    if (b == 0) {
        for (long long e = nout + (long long)BB * LEN + tid; e < out_elems; e += 256)
            out[e] = 1.0f;
    }
}

// ---------------------------------------------------------------------------
// Kernel 2: gather-pool. One block per (b, seg); 288 threads, one float4 each.
__global__ __launch_bounds__(HV) void k_pool(const float* __restrict__ hs,
                                             float* __restrict__ out,
                                             long long out_elems) {
    const int bs = blockIdx.x;                 // 0 .. B*LEN-1
    const int b  = bs >> 10;                   // LEN = 1024
    int cnt = g_counts[bs];
    if (cnt > K2) cnt = K2;

    // Sorted source list -> deterministic fp32 summation order
    // (atomicAdd slot order is not deterministic).
    int idxs[K2];
    #pragma unroll
    for (int j = 0; j < K2; j++)
        idxs[j] = (j < cnt) ? g_lists[bs * K2 + j] : 0x7FFFFFFF;
    #pragma unroll
    for (int a = 0; a < K2; a++)
        #pragma unroll
        for (int c = a + 1; c < K2; c++)
            if (idxs[c] < idxs[a]) { int t = idxs[a]; idxs[a] = idxs[c]; idxs[c] = t; }

    const int t = threadIdx.x;
    const float4* base = (const float4*)(hs) + (size_t)b * SS * HV;
    const float scale = 8.485281374238571f;    // sqrt(1152) / 4
    float4 acc = make_float4(0.f, 0.f, 0.f, 0.f);

    if (cnt == K2) {
        // dominant uniform path: 4 unconditional streaming loads (full MLP)
        float4 v0 = __ldcs(&base[(size_t)idxs[0] * HV + t]);
        float4 v1 = __ldcs(&base[(size_t)idxs[1] * HV + t]);
        float4 v2 = __ldcs(&base[(size_t)idxs[2] * HV + t]);
        float4 v3 = __ldcs(&base[(size_t)idxs[3] * HV + t]);
        acc.x = ((v0.x + v1.x) + (v2.x + v3.x));
        acc.y = ((v0.y + v1.y) + (v2.y + v3.y));
        acc.z = ((v0.z + v1.z) + (v2.z + v3.z));
        acc.w = ((v0.w + v1.w) + (v2.w + v3.w));
    } else {
        #pragma unroll
        for (int j = 0; j < K2; j++) {
            if (j < cnt && idxs[j] < SS) {
                float4 v = __ldcs(&base[(size_t)idxs[j] * HV + t]);
                acc.x += v.x; acc.y += v.y; acc.z += v.z; acc.w += v.w;
            }
        }
    }
    acc.x *= scale; acc.y *= scale; acc.z *= scale; acc.w *= scale;

    long long e = (long long)bs * HH + (long long)t * 4;
    if (e + 3 < out_elems) {
        __stcs(&((float4*)out)[(size_t)bs * HV + t], acc);
    } else {
        float v[4] = {acc.x, acc.y, acc.z, acc.w};
        #pragma unroll
        for (int q = 0; q < 4; q++)
            if (e + q < out_elems) out[e + q] = v[q];
    }
}

// ---------------------------------------------------------------------------
extern "C" void kernel_launch(void* const* d_in, const int* in_sizes, int n_in,
                              void* d_out, int out_size) {
    if (n_in < 2 || !d_in || !d_out) return;
    const float* hs  = (const float*)d_in[0];
    const int*   pos = (const int*)d_in[1];
    int npos = in_sizes[1];
    float* out = (float*)d_out;
    long long out_elems = (long long)out_size;

    k_index<<<BB, 256>>>(pos, npos, out, out_elems);
    k_pool<<<BB * LEN, HV>>>(hs, out, out_elems);
}

// round 7
// speedup vs baseline: 1.2431x; 1.0943x over previous
#include <cuda_runtime.h>
#include <cuda_bf16.h>
#include <math.h>

// Problem constants (fixed by setup_inputs)
#define BB   8
#define SS   4096
#define HH   1152
#define LEN  1024
#define KK   2          // pooling factor k = sqrt(S/LEN)
#define K2   4          // k*k
#define HV   (HH/4)     // float4 chunks per row = 288

// Scratch (allocation-free rule: __device__ globals).
// Invariant: g_maxx[] == 0 at every kernel_launch entry (module-load zero init;
// k_pool resets it at the end of each launch sequence). Everything is fully
// recomputed every call — no caching, deterministic.
__device__ int g_counts[BB * LEN];
__device__ int g_lists[BB * LEN * K2];
__device__ int g_maxx[BB];

// ---------------------------------------------------------------------------
// Kernel 1: zero counts + per-batch max_x. Grid 64 x 256 = 16384 threads.
// Each block covers 512 consecutive positions -> all in one batch
// (4096 per batch / 512 = 8 blocks per batch). One atomicMax per block.
__global__ __launch_bounds__(256) void k_max(const int* __restrict__ pos, int npos) {
    const int tid = blockIdx.x * 256 + threadIdx.x;
    if (tid < BB * LEN) g_counts[tid] = 0;

    const int b = blockIdx.x >> 3;                // 8 blocks per batch
    int m = 0;
    #pragma unroll
    for (int q = 0; q < 2; q++) {
        int i = tid * 2 + q;                      // position index 0..BB*SS-1
        long long off = (long long)i * 2;
        int x = (off < npos && i < BB * SS) ? pos[off] : 0;
        if (x < 0) x = 0;
        m = max(m, x);
    }
    for (int o = 16; o > 0; o >>= 1)
        m = max(m, __shfl_xor_sync(0xFFFFFFFFu, m, o));
    __shared__ int s_max[8];
    if ((threadIdx.x & 31) == 0) s_max[threadIdx.x >> 5] = m;
    __syncthreads();
    if (threadIdx.x == 0) {
        int r = s_max[0];
        for (int w = 1; w < 8; w++) r = max(r, s_max[w]);
        atomicMax(&g_maxx[b], r);
    }
}

// ---------------------------------------------------------------------------
// Kernel 2: build per-segment lists with global atomics. Grid 128 x 256.
__global__ __launch_bounds__(256) void k_build(const int* __restrict__ pos, int npos,
                                               float* __restrict__ out,
                                               long long out_elems) {
    const int i = blockIdx.x * 256 + threadIdx.x;   // 0..BB*SS-1
    if (i < BB * SS) {
        const int b = i >> 12;                      // SS = 4096
        long long off = (long long)i * 2;
        int x = (off + 1 < npos) ? pos[off]     : 0;
        int y = (off + 1 < npos) ? pos[off + 1] : 0;
        if (x < 0) x = 0;
        if (y < 0) y = 0;
        const int mw = (g_maxx[b] + 1) / KK;        // (max_x+1)//k
        int seg = (x / KK) + mw * (y / KK);
        if (seg < 0) seg = 0;
        if (seg >= LEN) seg = LEN - 1;
        int slot = atomicAdd(&g_counts[b * LEN + seg], 1);
        if (slot < K2) g_lists[(b * LEN + seg) * K2 + slot] = i - (b << 12);
    }
    // defensive fill of any out tail beyond pooled tensor + mask
    if (blockIdx.x == 0) {
        const long long start = (long long)BB * LEN * HH + (long long)BB * LEN;
        for (long long e = start + threadIdx.x; e < out_elems; e += 256)
            out[e] = 1.0f;
    }
}

// ---------------------------------------------------------------------------
// Kernel 3: gather-pool. One block per SEGMENT PAIR; 288 threads, each thread
// issues 8 independent float4 streaming loads (MLP=8), 2 stores.
// Also writes the mask tail and resets g_maxx for the next launch.
__global__ __launch_bounds__(HV) void k_pool(const float* __restrict__ hs,
                                             float* __restrict__ out,
                                             long long out_elems) {
    const int blk = blockIdx.x;                 // 0 .. B*LEN/2 - 1
    const int bs0 = blk * 2;
    const int bs1 = bs0 + 1;
    const int b   = blk >> 9;                   // 512 pairs per batch

    int cnt0 = g_counts[bs0]; if (cnt0 > K2) cnt0 = K2;
    int cnt1 = g_counts[bs1]; if (cnt1 > K2) cnt1 = K2;

    // Sorted source lists -> deterministic fp32 summation order.
    int ia[K2], ib[K2];
    #pragma unroll
    for (int j = 0; j < K2; j++) {
        ia[j] = (j < cnt0) ? g_lists[bs0 * K2 + j] : 0x7FFFFFFF;
        ib[j] = (j < cnt1) ? g_lists[bs1 * K2 + j] : 0x7FFFFFFF;
    }
    #pragma unroll
    for (int a = 0; a < K2; a++)
        #pragma unroll
        for (int c = a + 1; c < K2; c++) {
            if (ia[c] < ia[a]) { int t = ia[a]; ia[a] = ia[c]; ia[c] = t; }
            if (ib[c] < ib[a]) { int t = ib[a]; ib[a] = ib[c]; ib[c] = t; }
        }

    const int t = threadIdx.x;
    const float4* base = (const float4*)(hs) + (size_t)b * SS * HV;
    const float scale = 8.485281374238571f;     // sqrt(1152) / 4
    float4 acc0 = make_float4(0.f, 0.f, 0.f, 0.f);
    float4 acc1 = make_float4(0.f, 0.f, 0.f, 0.f);

    if (cnt0 == K2 && cnt1 == K2) {
        // dominant path: 8 unconditional streaming loads in flight
        float4 a0 = __ldcs(&base[(size_t)ia[0] * HV + t]);
        float4 a1 = __ldcs(&base[(size_t)ia[1] * HV + t]);
        float4 a2 = __ldcs(&base[(size_t)ia[2] * HV + t]);
        float4 a3 = __ldcs(&base[(size_t)ia[3] * HV + t]);
        float4 c0 = __ldcs(&base[(size_t)ib[0] * HV + t]);
        float4 c1 = __ldcs(&base[(size_t)ib[1] * HV + t]);
        float4 c2 = __ldcs(&base[(size_t)ib[2] * HV + t]);
        float4 c3 = __ldcs(&base[(size_t)ib[3] * HV + t]);
        acc0.x = (a0.x + a1.x) + (a2.x + a3.x);
        acc0.y = (a0.y + a1.y) + (a2.y + a3.y);
        acc0.z = (a0.z + a1.z) + (a2.z + a3.z);
        acc0.w = (a0.w + a1.w) + (a2.w + a3.w);
        acc1.x = (c0.x + c1.x) + (c2.x + c3.x);
        acc1.y = (c0.y + c1.y) + (c2.y + c3.y);
        acc1.z = (c0.z + c1.z) + (c2.z + c3.z);
        acc1.w = (c0.w + c1.w) + (c2.w + c3.w);
    } else {
        #pragma unroll
        for (int j = 0; j < K2; j++) {
            if (j < cnt0 && ia[j] < SS) {
                float4 v = __ldcs(&base[(size_t)ia[j] * HV + t]);
                acc0.x += v.x; acc0.y += v.y; acc0.z += v.z; acc0.w += v.w;
            }
            if (j < cnt1 && ib[j] < SS) {
                float4 v = __ldcs(&base[(size_t)ib[j] * HV + t]);
                acc1.x += v.x; acc1.y += v.y; acc1.z += v.z; acc1.w += v.w;
            }
        }
    }
    acc0.x *= scale; acc0.y *= scale; acc0.z *= scale; acc0.w *= scale;
    acc1.x *= scale; acc1.y *= scale; acc1.z *= scale; acc1.w *= scale;

    long long e0 = (long long)bs0 * HH + (long long)t * 4;
    long long e1 = (long long)bs1 * HH + (long long)t * 4;
    if (e0 + 3 < out_elems) __stcs(&((float4*)out)[(size_t)bs0 * HV + t], acc0);
    else {
        float v[4] = {acc0.x, acc0.y, acc0.z, acc0.w};
        #pragma unroll
        for (int q = 0; q < 4; q++) if (e0 + q < out_elems) out[e0 + q] = v[q];
    }
    if (e1 + 3 < out_elems) __stcs(&((float4*)out)[(size_t)bs1 * HV + t], acc1);
    else {
        float v[4] = {acc1.x, acc1.y, acc1.z, acc1.w};
        #pragma unroll
        for (int q = 0; q < 4; q++) if (e1 + q < out_elems) out[e1 + q] = v[q];
    }

    // mask tail (counts are final here)
    const long long nout = (long long)BB * LEN * HH;
    if (t == 0 && nout + bs0 < out_elems) out[nout + bs0] = (cnt0 > 0) ? 1.0f : 0.0f;
    if (t == 1 && nout + bs1 < out_elems) out[nout + bs1] = (cnt1 > 0) ? 1.0f : 0.0f;

    // reset g_maxx for the next launch (maintains the entry invariant)
    if (t == 2 && blk < BB) g_maxx[blk] = 0;
}

// ---------------------------------------------------------------------------
extern "C" void kernel_launch(void* const* d_in, const int* in_sizes, int n_in,
                              void* d_out, int out_size) {
    if (n_in < 2 || !d_in || !d_out) return;
    const float* hs  = (const float*)d_in[0];
    const int*   pos = (const int*)d_in[1];
    int npos = in_sizes[1];
    float* out = (float*)d_out;
    long long out_elems = (long long)out_size;

    k_max<<<64, 256>>>(pos, npos);
    k_build<<<128, 256>>>(pos, npos, out, out_elems);
    k_pool<<<BB * LEN / 2, HV>>>(hs, out, out_elems);
}